// round 13
// baseline (speedup 1.0000x reference)
#include <cuda_runtime.h>
#include <cuda_fp16.h>
#include <cuda_pipeline.h>
#include <cstdint>

// LUTBlock: out[b,o] = sum_{t=0..15} table[t, idx[b,t], o]
// idx[b,t] = sum_c ((x[b, aa[t,c]] - x[b, ab[t,c]]) > 0) << c
//
// R13: single persistent kernel. Phase A: all 1184 CTAs cooperatively
// convert the fp32 table to the fp16 scratch; monotonic-epoch software grid
// barrier (one wave -> co-residency guaranteed, replay-safe, no reset);
// Phase B: R12's persistent gather loop (cp.async x pipeline, ballot
// indices, two 8x LDG.64 waves + HADD2 tree). Removes the separate pre-pass
// launch + gap (~6.7us serialized overhead).

#define B_SZ    16384
#define IN_F    1024
#define OUT_F   1024
#define T_CNT   16
#define GRID_MAIN 1184          // 148 SMs x 8 CTAs: exactly one wave

#define TABLE_ELEMS (16 * 256 * 1024)   // 4M elements

// 8 MB fp16 scratch copy of the table (device global: allocation-free).
__device__ __half g_table_h[TABLE_ELEMS];

// Grid-barrier state: monotonic across graph replays (no reset needed).
__device__ unsigned g_arrive = 0;
__device__ volatile unsigned g_release = 0;

// ---------------------------------------------------------------------------
// Reduce 8 table values (uint2 of 4 halves) with a depth-2 fp16 tree,
// accumulating the two quad partials into fp32 acc. (rel_err ~3.8e-4)
// ---------------------------------------------------------------------------
__device__ __forceinline__ void reduce8(const uint2* __restrict__ v, float4& acc)
{
#define H2(u) (*reinterpret_cast<const half2*>(&(u)))
    half2 p0 = __hadd2(H2(v[0].x), H2(v[1].x));
    half2 p1 = __hadd2(H2(v[2].x), H2(v[3].x));
    half2 p2 = __hadd2(H2(v[4].x), H2(v[5].x));
    half2 p3 = __hadd2(H2(v[6].x), H2(v[7].x));
    half2 qx0 = __hadd2(p0, p1);
    half2 qx1 = __hadd2(p2, p3);
    half2 r0 = __hadd2(H2(v[0].y), H2(v[1].y));
    half2 r1 = __hadd2(H2(v[2].y), H2(v[3].y));
    half2 r2 = __hadd2(H2(v[4].y), H2(v[5].y));
    half2 r3 = __hadd2(H2(v[6].y), H2(v[7].y));
    half2 qy0 = __hadd2(r0, r1);
    half2 qy1 = __hadd2(r2, r3);
#undef H2
    const float2 fx0 = __half22float2(qx0);
    const float2 fx1 = __half22float2(qx1);
    const float2 fy0 = __half22float2(qy0);
    const float2 fy1 = __half22float2(qy1);
    acc.x += fx0.x + fx1.x;
    acc.y += fx0.y + fx1.y;
    acc.z += fy0.x + fy1.x;
    acc.w += fy0.y + fy1.y;
}

// ---------------------------------------------------------------------------
// Fused persistent kernel: 256 threads, occ 8, grid = one wave (1184).
// ---------------------------------------------------------------------------
__global__ __launch_bounds__(256, 8)
void lut_fused_kernel(const float4* __restrict__ x4,
                      const float4* __restrict__ table4,
                      const int* __restrict__ aa,
                      const int* __restrict__ ab,
                      float4* __restrict__ out4)
{
    __shared__ float s_x[3][IN_F];
    __shared__ __align__(16) unsigned s_pk[2][4];

    const int tid  = threadIdx.x;
    const int lane = tid & 31;
    const int b0   = blockIdx.x;

    // ---- Prologue: start x prefetch for first two batches (overlaps
    //      conversion + barrier below). cp.async groups 0 and 1.
    __pipeline_memcpy_async(&reinterpret_cast<float4*>(s_x[0])[tid],
                            &x4[(size_t)b0 * (IN_F / 4) + tid], 16);
    __pipeline_commit();
    {
        const int b1 = b0 + GRID_MAIN;
        if (b1 < B_SZ)
            __pipeline_memcpy_async(&reinterpret_cast<float4*>(s_x[1])[tid],
                                    &x4[(size_t)b1 * (IN_F / 4) + tid], 16);
        __pipeline_commit();
    }

    // ---- Phase A: cooperative table conversion (grid-stride over uint4
    //      chunks of 8 elems; 512K chunks / 303104 threads -> 1-2 iters).
    {
        const int gthreads = GRID_MAIN * 256;
        for (int i = b0 * 256 + tid; i < TABLE_ELEMS / 8; i += gthreads) {
            const float4 v0 = __ldg(&table4[2 * i + 0]);
            const float4 v1 = __ldg(&table4[2 * i + 1]);
            half2 h[4];
            h[0] = __floats2half2_rn(v0.x, v0.y);
            h[1] = __floats2half2_rn(v0.z, v0.w);
            h[2] = __floats2half2_rn(v1.x, v1.y);
            h[3] = __floats2half2_rn(v1.z, v1.w);
            reinterpret_cast<uint4*>(g_table_h)[i] = *reinterpret_cast<const uint4*>(h);
        }
    }

    // ---- Grid barrier (monotonic epoch; replay-safe; one wave => no deadlock)
    __syncthreads();                    // CTA's converters done
    if (tid == 0) {
        __threadfence();                // publish this CTA's table writes
        const unsigned ticket = atomicAdd(&g_arrive, 1u);
        const unsigned epoch  = ticket / GRID_MAIN;
        if ((ticket % GRID_MAIN) == GRID_MAIN - 1u) {
            g_release = epoch + 1u;     // last arriver releases
        } else {
            while (g_release <= epoch) __nanosleep(200);
        }
    }
    __syncthreads();                    // whole CTA sees the release

    // ---- Phase B: persistent gather loop (identical to R12).
    int ia = 0, ibx = 0;
    if (tid < 128) {
        ia  = __ldg(&aa[tid]);
        ibx = __ldg(&ab[tid]);
    }
    const char* tbase = reinterpret_cast<const char*>(g_table_h) + tid * 8;

    __pipeline_wait_prior(1);           // b0's x tile resident
    __syncthreads();

    int cur = 0;
    int par = 0;
    for (int b = b0; b < B_SZ; b += GRID_MAIN) {
        // 1. prefetch batch b + 2*GRID (depth-2 pipeline; empty group if OOB)
        {
            const int b2 = b + 2 * GRID_MAIN;
            int nxt2 = cur + 2; if (nxt2 >= 3) nxt2 -= 3;
            if (b2 < B_SZ)
                __pipeline_memcpy_async(&reinterpret_cast<float4*>(s_x[nxt2])[tid],
                                        &x4[(size_t)b2 * (IN_F / 4) + tid], 16);
            __pipeline_commit();
        }

        // 2. ballot: warp w's word = packed index bytes for t = 4w..4w+3
        if (tid < 128) {
            const float* xr = s_x[cur];
            const float d = xr[ia] - xr[ibx];
            const unsigned m = __ballot_sync(0xFFFFFFFFu, d > 0.0f);
            if (lane == 0) s_pk[par][tid >> 5] = m;
        }

        // 3. ensure next batch's x tile has landed; publish indices
        __pipeline_wait_prior(1);
        __syncthreads();

        // 4. gather-sum from fp16 table (L2-resident), two 8-load waves
        const uint4 pk = *reinterpret_cast<const uint4*>(s_pk[par]);
        float4 acc = make_float4(0.f, 0.f, 0.f, 0.f);
        {   // wave A: t = 0..7
            uint2 v[8];
#pragma unroll
            for (int t = 0; t < 8; t++) {
                const unsigned wd = (t < 4) ? pk.x : pk.y;
                const unsigned r = __byte_perm(wd, 0u, 0x4440 + (t & 3));
                v[t] = __ldg(reinterpret_cast<const uint2*>(
                                 tbase + (size_t)t * 524288u + r * 2048u));
            }
            reduce8(v, acc);
        }
        {   // wave B: t = 8..15
            uint2 v[8];
#pragma unroll
            for (int t = 0; t < 8; t++) {
                const unsigned wd = (t < 4) ? pk.z : pk.w;
                const unsigned r = __byte_perm(wd, 0u, 0x4440 + (t & 3));
                v[t] = __ldg(reinterpret_cast<const uint2*>(
                                 tbase + (size_t)(t + 8) * 524288u + r * 2048u));
            }
            reduce8(v, acc);
        }
        out4[(size_t)b * (OUT_F / 4) + tid] = acc;

        cur = (cur + 1 == 3) ? 0 : cur + 1;
        par ^= 1;
    }
}

extern "C" void kernel_launch(void* const* d_in, const int* in_sizes, int n_in,
                              void* d_out, int out_size)
{
    const float4* x4     = (const float4*)d_in[0];  // (B, IN_F) fp32
    const float4* table4 = (const float4*)d_in[1];  // (T, R, OUT_F) fp32
    const int*    aa     = (const int*)   d_in[2];  // (T, C) int32
    const int*    ab     = (const int*)   d_in[3];  // (T, C) int32
    float4*       out4   = (float4*)      d_out;    // (B, OUT_F) fp32

    (void)in_sizes; (void)n_in; (void)out_size;

    // Single fused persistent kernel: convert + barrier + gather.
    lut_fused_kernel<<<GRID_MAIN, 256>>>(x4, table4, aa, ab, out4);
}